// round 12
// baseline (speedup 1.0000x reference)
#include <cuda_runtime.h>
#include <cuda_bf16.h>
#include <math.h>
#include <cstdint>

#define BATCH 16384
__device__ __nv_bfloat16 g_latent_bf[BATCH * 224];
__device__ __nv_bfloat16 g_hbf[BATCH * 392];

__device__ __forceinline__ uint32_t smem_u32(const void* p) {
    uint32_t a;
    asm("{ .reg .u64 t; cvta.to.shared.u64 t, %1; cvt.u32.u64 %0, t; }" : "=r"(a) : "l"(p));
    return a;
}
__device__ __forceinline__ void ldmatrix_x4(uint32_t& r0, uint32_t& r1, uint32_t& r2, uint32_t& r3,
                                            uint32_t addr) {
    asm volatile("ldmatrix.sync.aligned.m8n8.x4.shared.b16 {%0,%1,%2,%3}, [%4];"
                 : "=r"(r0), "=r"(r1), "=r"(r2), "=r"(r3) : "r"(addr));
}
__device__ __forceinline__ void mma_16816(float* d, const uint32_t* a, const uint32_t* b) {
    asm volatile(
        "mma.sync.aligned.m16n8k16.row.col.f32.bf16.bf16.f32 "
        "{%0,%1,%2,%3}, {%4,%5,%6,%7}, {%8,%9}, {%0,%1,%2,%3};"
        : "+f"(d[0]), "+f"(d[1]), "+f"(d[2]), "+f"(d[3])
        : "r"(a[0]), "r"(a[1]), "r"(a[2]), "r"(a[3]), "r"(b[0]), "r"(b[1]));
}

// ---------------------------------------------------------------------------
// Kernel 1: 32 samples per 256-thread block.
//  Phase 1: 8 threads/sample quadrant reduce; Phase 2: warp 0 sim (lane=sample);
//  Phase 3: latent GEMV, bf16x2 stores.
// ---------------------------------------------------------------------------
__global__ void __launch_bounds__(256) k1_quad_latent(
    const float* __restrict__ x,
    const float* __restrict__ var_params,
    const float* __restrict__ w_lat,
    const float* __restrict__ b_lat)
{
    __shared__ float sang[32][4];
    __shared__ float sz[32][4];
    __shared__ float4 swlat[224];
    __shared__ float sbl[224];

    const int tid = threadIdx.x;
    const int b0 = blockIdx.x * 32;
    const int s = tid >> 3;
    const int sub = tid & 7;

    if (tid < 224) {
        swlat[tid] = *(const float4*)(w_lat + tid * 4);
        sbl[tid] = b_lat[tid];
    }

    {
        const float4* xb4 = (const float4*)(x + (size_t)(b0 + s) * 784);
        float q0 = 0.f, q1 = 0.f, q2 = 0.f, q3 = 0.f;
#pragma unroll
        for (int it = 0; it < 25; it++) {
            int f = sub + 8 * it;
            if (f < 196) {
                float4 v = xb4[f];
                int row = f / 7;
                int cg  = f - row * 7;
                float s4  = (v.x + v.y) + (v.z + v.w);
                float lft = (cg < 3) ? s4 : ((cg == 3) ? (v.x + v.y) : 0.f);
                float rgt = s4 - lft;
                if (row < 14) { q0 += lft; q1 += rgt; }
                else          { q2 += lft; q3 += rgt; }
            }
        }
#pragma unroll
        for (int off = 4; off; off >>= 1) {
            q0 += __shfl_xor_sync(0xFFFFFFFFu, q0, off);
            q1 += __shfl_xor_sync(0xFFFFFFFFu, q1, off);
            q2 += __shfl_xor_sync(0xFFFFFFFFu, q2, off);
            q3 += __shfl_xor_sync(0xFFFFFFFFu, q3, off);
        }
        if (sub == 0) {
            const float inv196 = 1.0f / 196.0f;
            sang[s][0] = q0 * inv196;
            sang[s][1] = q1 * inv196;
            sang[s][2] = q2 * inv196;
            sang[s][3] = q3 * inv196;
        }
    }
    __syncthreads();

    if (tid < 32) {
        float cc[4], ss[4];
#pragma unroll
        for (int q = 0; q < 4; q++) {
            float th = 0.5f * sang[tid][q];
            cc[q] = __cosf(th);
            ss[q] = __sinf(th);
        }
        float re[16], im[16];
#pragma unroll
        for (int i = 0; i < 16; i++) {
            re[i] = ((i & 8) ? ss[0] : cc[0]) * ((i & 4) ? ss[1] : cc[1]) *
                    ((i & 2) ? ss[2] : cc[2]) * ((i & 1) ? ss[3] : cc[3]);
            im[i] = 0.f;
        }
#pragma unroll
        for (int q = 0; q < 4; q++) {
            float ph = 0.5f * var_params[q];
            float hcv = __cosf(ph), hsv = __sinf(ph);
            const int mq = 8 >> q;
            const int mt = 8 >> ((q + 1) & 3);
#pragma unroll
            for (int i = 0; i < 16; i++) {
                float sg = (i & mq) ? hsv : -hsv;
                float nr = re[i] * hcv - im[i] * sg;
                float ni = re[i] * sg + im[i] * hcv;
                re[i] = nr; im[i] = ni;
            }
#pragma unroll
            for (int i = 0; i < 16; i++) {
                if ((i & mq) && !(i & mt)) {
                    int j2 = i | mt;
                    float tr = re[i]; re[i] = re[j2]; re[j2] = tr;
                    float ti = im[i]; im[i] = im[j2]; im[j2] = ti;
                }
            }
        }
        float z0 = 0.f, z1 = 0.f, z2 = 0.f, z3 = 0.f;
#pragma unroll
        for (int i = 0; i < 16; i++) {
            float p = re[i] * re[i] + im[i] * im[i];
            z0 += (i & 8) ? -p : p;
            z1 += (i & 4) ? -p : p;
            z2 += (i & 2) ? -p : p;
            z3 += (i & 1) ? -p : p;
        }
        sz[tid][0] = z0; sz[tid][1] = z1; sz[tid][2] = z2; sz[tid][3] = z3;
    }
    __syncthreads();

    __nv_bfloat162* lat2 = (__nv_bfloat162*)g_latent_bf;
    for (int idx = tid; idx < 32 * 112; idx += 256) {
        int ls = idx / 112;
        int rp = idx - ls * 112;
        int r = rp * 2;
        float4 zv = *(const float4*)sz[ls];
        float4 w0 = swlat[r];
        float4 w1 = swlat[r + 1];
        float a0 = sbl[r];
        a0 = fmaf(w0.x, zv.x, a0); a0 = fmaf(w0.y, zv.y, a0);
        a0 = fmaf(w0.z, zv.z, a0); a0 = fmaf(w0.w, zv.w, a0);
        float a1 = sbl[r + 1];
        a1 = fmaf(w1.x, zv.x, a1); a1 = fmaf(w1.y, zv.y, a1);
        a1 = fmaf(w1.z, zv.z, a1); a1 = fmaf(w1.w, zv.w, a1);
        __nv_bfloat162 o;
        o.x = __float2bfloat16(fmaxf(a0, 0.f));
        o.y = __float2bfloat16(fmaxf(a1, 0.f));
        lat2[(size_t)(b0 + ls) * 112 + rp] = o;
    }
}

// ---------------------------------------------------------------------------
// Kernel 2: HMMA bf16 GEMM: h = relu(latent @ w_fc^T + b_fc), h stored bf16.
// B staged directly from fp32 w_fc with on-the-fly bf16 convert (no k2a).
// ---------------------------------------------------------------------------
#define ASTR 232
#define K2_SMEM_BYTES ((128 * ASTR + 64 * ASTR) * 2)

__global__ void __launch_bounds__(256, 2) k2_gemm_mma(
    const float* __restrict__ w_fc,
    const float* __restrict__ b_fc)
{
    extern __shared__ __align__(16) __nv_bfloat16 sm[];
    __nv_bfloat16* sa = sm;               // [128][ASTR]
    __nv_bfloat16* sb = sm + 128 * ASTR;  // [64][ASTR]

    const int tid = threadIdx.x;
    const int wid = tid >> 5;
    const int lane = tid & 31;
    const int n0 = blockIdx.x * 64;
    const int m0 = blockIdx.y * 128;
    const int mw = (wid & 3) * 32;
    const int nw = (wid >> 2) * 32;

    for (int t = tid; t < 128 * 28; t += 256) {
        int r = t / 28, c = t - (t / 28) * 28;
        uint4 v = *(const uint4*)(g_latent_bf + (size_t)(m0 + r) * 224 + c * 8);
        *(uint4*)(sa + r * ASTR + c * 8) = v;
    }
    // B: stage from fp32 with convert; float4 granularity (4 bf16 out)
    for (int t = tid; t < 64 * 56; t += 256) {
        int r = t / 56, c4 = t - (t / 56) * 56;
        int gn = n0 + r;
        float4 v = make_float4(0.f, 0.f, 0.f, 0.f);
        if (gn < 392) v = *(const float4*)(w_fc + (size_t)gn * 224 + c4 * 4);
        __nv_bfloat162 lo, hi;
        lo.x = __float2bfloat16(v.x); lo.y = __float2bfloat16(v.y);
        hi.x = __float2bfloat16(v.z); hi.y = __float2bfloat16(v.w);
        *(__nv_bfloat162*)(sb + r * ASTR + c4 * 4)     = lo;
        *(__nv_bfloat162*)(sb + r * ASTR + c4 * 4 + 2) = hi;
    }
    __syncthreads();

    float d[2][4][4];
#pragma unroll
    for (int mt = 0; mt < 2; mt++)
#pragma unroll
        for (int nt = 0; nt < 4; nt++)
#pragma unroll
            for (int e = 0; e < 4; e++) d[mt][nt][e] = 0.f;

    const uint32_t sa_base = smem_u32(sa);
    const uint32_t sb_base = smem_u32(sb);
    const int a_row = mw + (lane & 15);
    const int a_coff = (lane >> 4) * 8;
    const int b_row = nw + (lane & 7) + ((lane >> 4) & 1) * 8;
    const int b_coff = ((lane >> 3) & 1) * 8;

#pragma unroll
    for (int ks = 0; ks < 14; ks++) {
        const int k0 = ks * 16;
        uint32_t a0[4], a1[4];
        ldmatrix_x4(a0[0], a0[1], a0[2], a0[3],
                    sa_base + (uint32_t)((a_row) * ASTR + k0 + a_coff) * 2);
        ldmatrix_x4(a1[0], a1[1], a1[2], a1[3],
                    sa_base + (uint32_t)((a_row + 16) * ASTR + k0 + a_coff) * 2);
        uint32_t b01[4], b23[4];
        ldmatrix_x4(b01[0], b01[1], b01[2], b01[3],
                    sb_base + (uint32_t)((b_row) * ASTR + k0 + b_coff) * 2);
        ldmatrix_x4(b23[0], b23[1], b23[2], b23[3],
                    sb_base + (uint32_t)((b_row + 16) * ASTR + k0 + b_coff) * 2);
        mma_16816(d[0][0], a0, b01 + 0);
        mma_16816(d[0][1], a0, b01 + 2);
        mma_16816(d[0][2], a0, b23 + 0);
        mma_16816(d[0][3], a0, b23 + 2);
        mma_16816(d[1][0], a1, b01 + 0);
        mma_16816(d[1][1], a1, b01 + 2);
        mma_16816(d[1][2], a1, b23 + 0);
        mma_16816(d[1][3], a1, b23 + 2);
    }

    const int qrow = lane >> 2;
    const int qcol = (lane & 3) * 2;
#pragma unroll
    for (int nt = 0; nt < 4; nt++) {
        int gn = n0 + nw + nt * 8 + qcol;
        if (gn < 392) {
            float2 bv = *(const float2*)(b_fc + gn);
#pragma unroll
            for (int mt = 0; mt < 2; mt++) {
                int m = m0 + mw + mt * 16 + qrow;
                __nv_bfloat162 o0, o1;
                o0.x = __float2bfloat16(fmaxf(d[mt][nt][0] + bv.x, 0.f));
                o0.y = __float2bfloat16(fmaxf(d[mt][nt][1] + bv.y, 0.f));
                o1.x = __float2bfloat16(fmaxf(d[mt][nt][2] + bv.x, 0.f));
                o1.y = __float2bfloat16(fmaxf(d[mt][nt][3] + bv.y, 0.f));
                *(__nv_bfloat162*)(g_hbf + (size_t)m * 392 + gn) = o0;
                *(__nv_bfloat162*)(g_hbf + (size_t)(m + 8) * 392 + gn) = o1;
            }
        }
    }
}

// ---------------------------------------------------------------------------
// Kernel 3: fused deconv1+relu+deconv2+sigmoid.
// Block = 256 threads / 10 samples. Each active thread processes TWO
// (s,i,j) items, sharing the warp-uniform weight loads between them.
// h read as bf16 (half the DRAM), converted to f32 smem during staging.
// ---------------------------------------------------------------------------
#define K3S 10
__global__ void __launch_bounds__(256) k3_deconv(
    const float* __restrict__ w_d1, const float* __restrict__ b_d1,
    const float* __restrict__ w_d2, const float* __restrict__ b_d2,
    float* __restrict__ out)
{
    __shared__ float shh[K3S * 392];
    __shared__ float sw1r[128];    // [c][p][o]
    __shared__ float sw2r[16];     // [dk][o]
    __shared__ float sb1v[4];
    __shared__ float sb2s;

    const int tid = threadIdx.x;
    const int b0 = blockIdx.x * K3S;
    const int nsamp = (BATCH - b0 < K3S) ? (BATCH - b0) : K3S;

    if (tid < 128) {
        int c = tid >> 4, p = (tid >> 2) & 3, o = tid & 3;
        sw1r[tid] = w_d1[c * 16 + o * 4 + p];
    } else if (tid < 144) {
        int t = tid - 128;
        sw2r[t] = w_d2[(t & 3) * 4 + (t >> 2)];
    } else if (tid < 148) sb1v[tid - 144] = b_d1[tid - 144];
    else if (tid == 148) sb2s = b_d2[0];

    // stage h: nsamp*49 chunks of 8 bf16, convert to f32 smem
    {
        const uint4* src = (const uint4*)(g_hbf + (size_t)b0 * 392);
        const int nch = nsamp * 49;
        for (int t = tid; t < nch; t += 256) {
            uint4 v = src[t];
            float* dp = shh + t * 8;
            __nv_bfloat162 p0 = *(__nv_bfloat162*)&v.x;
            __nv_bfloat162 p1 = *(__nv_bfloat162*)&v.y;
            __nv_bfloat162 p2 = *(__nv_bfloat162*)&v.z;
            __nv_bfloat162 p3 = *(__nv_bfloat162*)&v.w;
            dp[0] = __bfloat162float(p0.x); dp[1] = __bfloat162float(p0.y);
            dp[2] = __bfloat162float(p1.x); dp[3] = __bfloat162float(p1.y);
            dp[4] = __bfloat162float(p2.x); dp[5] = __bfloat162float(p2.y);
            dp[6] = __bfloat162float(p3.x); dp[7] = __bfloat162float(p3.y);
        }
    }
    __syncthreads();

    const int nitems = nsamp * 49;
    const int half = nitems >> 1;   // nitems always even (nsamp 10 or 4)
    if (tid < half) {
        const int i0 = tid, i1 = tid + half;
        const int s0 = i0 / 49, q0 = i0 - s0 * 49;
        const int s1 = i1 / 49, q1 = i1 - s1 * 49;
        const float* hp0 = shh + s0 * 392 + q0;
        const float* hp1 = shh + s1 * 392 + q1;

        float4 yv0[4], yv1[4];
#pragma unroll
        for (int p = 0; p < 4; p++) {
            float4 bi = make_float4(sb1v[0], sb1v[1], sb1v[2], sb1v[3]);
            yv0[p] = bi; yv1[p] = bi;
        }
#pragma unroll
        for (int c = 0; c < 8; c++) {
            float hv0 = hp0[c * 49];
            float hv1 = hp1[c * 49];
#pragma unroll
            for (int p = 0; p < 4; p++) {
                float4 wv = *(const float4*)(sw1r + (c * 4 + p) * 4);
                yv0[p].x = fmaf(hv0, wv.x, yv0[p].x);
                yv0[p].y = fmaf(hv0, wv.y, yv0[p].y);
                yv0[p].z = fmaf(hv0, wv.z, yv0[p].z);
                yv0[p].w = fmaf(hv0, wv.w, yv0[p].w);
                yv1[p].x = fmaf(hv1, wv.x, yv1[p].x);
                yv1[p].y = fmaf(hv1, wv.y, yv1[p].y);
                yv1[p].z = fmaf(hv1, wv.z, yv1[p].z);
                yv1[p].w = fmaf(hv1, wv.w, yv1[p].w);
            }
        }
#pragma unroll
        for (int p = 0; p < 4; p++) {
            yv0[p].x = fmaxf(yv0[p].x, 0.f); yv0[p].y = fmaxf(yv0[p].y, 0.f);
            yv0[p].z = fmaxf(yv0[p].z, 0.f); yv0[p].w = fmaxf(yv0[p].w, 0.f);
            yv1[p].x = fmaxf(yv1[p].x, 0.f); yv1[p].y = fmaxf(yv1[p].y, 0.f);
            yv1[p].z = fmaxf(yv1[p].z, 0.f); yv1[p].w = fmaxf(yv1[p].w, 0.f);
        }

#pragma unroll
        for (int which = 0; which < 2; which++) {
            const float4* yv = which ? yv1 : yv0;
            const int s = which ? s1 : s0;
            const int q = which ? q1 : q0;
            const int i = q / 7;
            const int j = q - i * 7;
            float* ob = out + (size_t)(b0 + s) * 784 + (4 * i) * 28 + 4 * j;
#pragma unroll
            for (int rr = 0; rr < 4; rr++) {
                const int d1 = rr >> 1, d2 = rr & 1;
                float4 w2a = *(const float4*)(sw2r + (d2 * 2 + 0) * 4);
                float4 w2b = *(const float4*)(sw2r + (d2 * 2 + 1) * 4);
                float4 v;
                {
                    float4 yp = yv[d1 * 2 + 0];
                    float a0 = sb2s, a1 = sb2s;
                    a0 = fmaf(yp.x, w2a.x, a0); a0 = fmaf(yp.y, w2a.y, a0);
                    a0 = fmaf(yp.z, w2a.z, a0); a0 = fmaf(yp.w, w2a.w, a0);
                    a1 = fmaf(yp.x, w2b.x, a1); a1 = fmaf(yp.y, w2b.y, a1);
                    a1 = fmaf(yp.z, w2b.z, a1); a1 = fmaf(yp.w, w2b.w, a1);
                    v.x = __fdividef(1.0f, 1.0f + __expf(-a0));
                    v.y = __fdividef(1.0f, 1.0f + __expf(-a1));
                }
                {
                    float4 yp = yv[d1 * 2 + 1];
                    float a0 = sb2s, a1 = sb2s;
                    a0 = fmaf(yp.x, w2a.x, a0); a0 = fmaf(yp.y, w2a.y, a0);
                    a0 = fmaf(yp.z, w2a.z, a0); a0 = fmaf(yp.w, w2a.w, a0);
                    a1 = fmaf(yp.x, w2b.x, a1); a1 = fmaf(yp.y, w2b.y, a1);
                    a1 = fmaf(yp.z, w2b.z, a1); a1 = fmaf(yp.w, w2b.w, a1);
                    v.z = __fdividef(1.0f, 1.0f + __expf(-a0));
                    v.w = __fdividef(1.0f, 1.0f + __expf(-a1));
                }
                *(float4*)(ob + (2 * d1 + d2) * 28) = v;
            }
        }
    }
}

// ---------------------------------------------------------------------------
// Launch
// ---------------------------------------------------------------------------
extern "C" void kernel_launch(void* const* d_in, const int* in_sizes, int n_in,
                              void* d_out, int out_size)
{
    const float* x          = (const float*)d_in[0];
    const float* var_params = (const float*)d_in[1];
    const float* w_lat      = (const float*)d_in[2];
    const float* b_lat      = (const float*)d_in[3];
    const float* w_fc       = (const float*)d_in[4];
    const float* b_fc       = (const float*)d_in[5];
    const float* w_d1       = (const float*)d_in[6];
    const float* b_d1       = (const float*)d_in[7];
    const float* w_d2       = (const float*)d_in[8];
    const float* b_d2       = (const float*)d_in[9];
    float* out = (float*)d_out;

    cudaFuncSetAttribute(k2_gemm_mma, cudaFuncAttributeMaxDynamicSharedMemorySize,
                         K2_SMEM_BYTES);

    k1_quad_latent<<<BATCH / 32, 256>>>(x, var_params, w_lat, b_lat);
    k2_gemm_mma<<<dim3(7, BATCH / 128), 256, K2_SMEM_BYTES>>>(w_fc, b_fc);
    k3_deconv<<<(BATCH + K3S - 1) / K3S, 256>>>(w_d1, b_d1, w_d2, b_d2, out);
}